// round 12
// baseline (speedup 1.0000x reference)
#include <cuda_runtime.h>
#include <cstdint>
#include <math.h>

// Problem constants (fixed by the dataset problem)
#define BATCH  16
#define NPTS   6890
#define NBUCK  2048
#define BSCALE 128.0f           // buckets per unit x: range [-8, 8) -> 2048
#define BOFF   8.0f

#define TPB     256
#define BPB     27              // blocks per batch
#define NBLK    (BATCH * BPB)   // 432 blocks; 4 CTAs/SM -> wave1 = 592 >= 432
#define ROWS_PB TPB             // 1 row per thread; 27*256 = 6912 >= 6890
#define NW      (TPB / 32)      // 8 warps per block

// ---- persistent device state (static globals; no allocation) ----
// g_hist: zero at entry (scan re-zeroes). g_pbar: phase-accumulating, never reset.
// g_min_i/g_arr: reset by the globally-last block. g_bbound: re-inited in P1.
__device__ int          g_hist[2][BATCH][NBUCK];
__device__ int          g_bstart[2][BATCH][NBUCK + 1];
__device__ int          g_cursor[2][BATCH][NBUCK];
__device__ float4       g_pts[2][BATCH][NPTS];     // sorted: (x, y, z, ||.||^2)
__device__ int          g_bbound[BATCH];           // per-batch bound bits
__device__ int          g_min_i = 0x7F800000;      // +inf bits
__device__ unsigned int g_pbar[BATCH][4];          // per-batch phase barriers
__device__ int          g_arr;                     // global arrival counter

__device__ __forceinline__ int bucket_of(float x) {
    int b = (int)((x + BOFF) * BSCALE);            // monotone map
    return min(max(b, 0), NBUCK - 1);
}

__device__ __forceinline__ unsigned int ld_acq(const unsigned int* p) {
    unsigned int v;
    asm volatile("ld.global.acquire.gpu.u32 %0, [%1];" : "=r"(v) : "l"(p) : "memory");
    return v;
}

// Per-batch barrier: count in bits[0:8), phase in bits[8:32). Last of BPB
// arrivers rolls count to 0 and bumps phase; spinners wait for phase to move.
// Phase accumulates across graph replays -> no reset needed.
__device__ __forceinline__ void pbar(int b, int k) {
    __syncthreads();
    if (threadIdx.x == 0) {
        __threadfence();
        unsigned int t = atomicAdd(&g_pbar[b][k], 1u);
        if ((t & 0xFFu) == (BPB - 1)) {
            atomicAdd(&g_pbar[b][k], 0x100u - BPB);   // count->0, phase+1
        } else {
            unsigned int ph = t >> 8;
            while ((ld_acq(&g_pbar[b][k]) >> 8) == ph) __nanosleep(32);
        }
        __threadfence();
    }
    __syncthreads();
}

// window min of (||q||^2 - 2 p.q) with 4 independent accumulators (MLP=4)
__device__ __forceinline__ float window_min(const float4* __restrict__ P,
                                            int lo, int hi,
                                            float nx, float ny, float nz)
{
    float m0 = INFINITY, m1 = INFINITY, m2 = INFINITY, m3 = INFINITY;
    int t = lo;
    for (; t + 4 <= hi; t += 4) {
        float4 q0 = P[t], q1 = P[t + 1], q2 = P[t + 2], q3 = P[t + 3];
        float d0 = fmaf(nx, q0.x, q0.w); d0 = fmaf(ny, q0.y, d0); d0 = fmaf(nz, q0.z, d0);
        float d1 = fmaf(nx, q1.x, q1.w); d1 = fmaf(ny, q1.y, d1); d1 = fmaf(nz, q1.z, d1);
        float d2 = fmaf(nx, q2.x, q2.w); d2 = fmaf(ny, q2.y, d2); d2 = fmaf(nz, q2.z, d2);
        float d3 = fmaf(nx, q3.x, q3.w); d3 = fmaf(ny, q3.y, d3); d3 = fmaf(nz, q3.z, d3);
        m0 = fminf(m0, d0); m1 = fminf(m1, d1);
        m2 = fminf(m2, d2); m3 = fminf(m3, d3);
    }
    for (; t < hi; t++) {
        float4 q = P[t];
        float d = fmaf(nx, q.x, q.w); d = fmaf(ny, q.y, d); d = fmaf(nz, q.z, d);
        m0 = fminf(m0, d);
    }
    return fminf(fminf(m0, m1), fminf(m2, m3));
}

__global__ __launch_bounds__(TPB, 4) void fused_kernel(
    const float* __restrict__ v1,
    const float* __restrict__ v2,
    float* __restrict__ out)
{
    const int b   = blockIdx.x / BPB;
    const int s   = blockIdx.x % BPB;
    const int tid = threadIdx.x, lane = tid & 31, wid = tid >> 5;
    const int row = s * ROWS_PB + tid;
    const bool rowact = (row < NPTS);

    __shared__ int   warpsum[NW];
    __shared__ float smin[NW];

    // ---------- P1: x-histogram of both clouds; re-init batch bound ----------
    if (s == 0 && tid == 0) g_bbound[b] = 0x7F800000;
    if (rowact) {
        float x1 = v1[((size_t)b * NPTS + row) * 3];
        atomicAdd(&g_hist[0][b][bucket_of(x1)], 1);
        float x2 = v2[((size_t)b * NPTS + row) * 3];
        atomicAdd(&g_hist[1][b][bucket_of(x2)], 1);
    }
    pbar(b, 0);

    // ---------- P2: scan (block s=0 -> cloud 0, s=1 -> cloud 1); zero hist ----------
    if (s < 2) {
        const int cloud = s;
        const int base = tid * 8;                  // 256 threads * 8 = 2048 buckets
        int a[8], sum = 0;
#pragma unroll
        for (int k = 0; k < 8; k++) {
            a[k] = g_hist[cloud][b][base + k];
            g_hist[cloud][b][base + k] = 0;        // restore invariant
            sum += a[k];
        }
        int v = sum;
#pragma unroll
        for (int o = 1; o < 32; o <<= 1) {
            int t = __shfl_up_sync(0xFFFFFFFFu, v, o);
            if (lane >= o) v += t;
        }
        if (lane == 31) warpsum[wid] = v;
        __syncthreads();
        // cross-warp scan: ALL 32 lanes run the shfl (no divergent-shfl hang);
        // lanes >= NW carry a 0 operand and store nothing.
        if (wid == 0) {
            int w = (lane < NW) ? warpsum[lane] : 0;
#pragma unroll
            for (int o = 1; o < NW; o <<= 1) {
                int t = __shfl_up_sync(0xFFFFFFFFu, w, o);
                if (lane >= o) w += t;
            }
            if (lane < NW) warpsum[lane] = w;
        }
        __syncthreads();
        int run = v - sum + ((wid > 0) ? warpsum[wid - 1] : 0);
#pragma unroll
        for (int k = 0; k < 8; k++) {
            g_bstart[cloud][b][base + k] = run;
            g_cursor[cloud][b][base + k] = run;
            run += a[k];
        }
        if (tid == 0) g_bstart[cloud][b][NBUCK] = NPTS;
    }
    pbar(b, 1);

    // ---------- P3: scatter both clouds into sorted float4 arrays ----------
    if (rowact) {
#pragma unroll
        for (int cloud = 0; cloud < 2; cloud++) {
            const float* src = cloud ? v2 : v1;
            const float* q = src + ((size_t)b * NPTS + row) * 3;
            float x = q[0], y = q[1], z = q[2];
            float qn = fmaf(z, z, fmaf(y, y, x * x));
            int pos = atomicAdd(&g_cursor[cloud][b][bucket_of(x)], 1);
            g_pts[cloud][b][pos] = make_float4(x, y, z, qn);
        }
    }
    pbar(b, 2);

    // ---------- P4: 3-bucket neighborhood pass (bound + bulk of prune) ----------
    float4 p = make_float4(0.f, 0.f, 0.f, 0.f);
    float nx = 0.f, ny = 0.f, nz = 0.f;
    int lo1 = 0, hi1 = 0;
    float vm = INFINITY;
    if (rowact) {
        p = g_pts[0][b][row];
        nx = -2.f * p.x; ny = -2.f * p.y; nz = -2.f * p.z;
        int bk = bucket_of(p.x);
        lo1 = g_bstart[1][b][max(bk - 1, 0)];
        hi1 = g_bstart[1][b][min(bk + 1, NBUCK - 1) + 1];
        vm = p.w + window_min(g_pts[1][b], lo1, hi1, nx, ny, nz);
    }
    {   // full-warp + block reduce (inactive lanes contribute INF)
        float t = vm;
#pragma unroll
        for (int o = 16; o; o >>= 1) t = fminf(t, __shfl_xor_sync(0xFFFFFFFFu, t, o));
        if (lane == 0) smin[wid] = t;
        __syncthreads();
        if (tid == 0) {
            float r = smin[0];
#pragma unroll
            for (int w = 1; w < NW; w++) r = fminf(r, smin[w]);
            if (r < INFINITY) atomicMin(&g_bbound[b], __float_as_int(r));
        }
    }
    pbar(b, 3);

    // ---------- P5: rare window extension + global reduce + output ----------
    {
        float usq = __int_as_float(g_bbound[b]);
        // slack covers fp32 dot-form cancellation at these magnitudes
        float U = sqrtf(fmaxf(usq, 0.f) + 3e-5f) * 1.0005f;
        if (rowact) {
            int lo2 = g_bstart[1][b][bucket_of(p.x - U)];
            int hi2 = g_bstart[1][b][bucket_of(p.x + U) + 1];
            if (lo2 < lo1)
                vm = fminf(vm, p.w + window_min(g_pts[1][b], lo2, lo1, nx, ny, nz));
            if (hi2 > hi1)
                vm = fminf(vm, p.w + window_min(g_pts[1][b], hi1, hi2, nx, ny, nz));
        }
#pragma unroll
        for (int o = 16; o; o >>= 1) vm = fminf(vm, __shfl_xor_sync(0xFFFFFFFFu, vm, o));
        __syncthreads();                      // smin reuse
        if (lane == 0) smin[wid] = vm;
        __syncthreads();
        if (tid == 0) {
            float r = smin[0];
#pragma unroll
            for (int w = 1; w < NW; w++) r = fminf(r, smin[w]);
            if (r < INFINITY) atomicMin(&g_min_i, __float_as_int(r));
            __threadfence();
            int a = atomicAdd(&g_arr, 1);
            if (a == NBLK - 1) {             // globally last block: emit + reset
                int mb = atomicAdd(&g_min_i, 0);
                out[0] = sqrtf(fmaxf(__int_as_float(mb), 0.f));
                g_min_i = 0x7F800000;
                g_arr = 0;
            }
        }
    }
}

extern "C" void kernel_launch(void* const* d_in, const int* in_sizes, int n_in,
                              void* d_out, int out_size)
{
    const float* v1 = (const float*)d_in[0];
    const float* v2 = (const float*)d_in[1];
    float* out = (float*)d_out;

    fused_kernel<<<NBLK, TPB>>>(v1, v2, out);
}